// round 13
// baseline (speedup 1.0000x reference)
#include <cuda_runtime.h>
#include <cuda_fp16.h>
#include <cstdint>

// ============================================================================
// BinaryConv2D: x(64,56,56,128) NHWC conv w(3,3,128,256) HWIO, SAME, stride 1.
// binarize both -> implicit GEMM on mma.sync m16n8k32 e4m3, F16 accumulate
// (exact: products ±1, partial sums are integers <= 1152 < 2048).
// == R13: ZERO-WASTE 8x8 pixel tiling (56 = 7x8 exactly; the old 8x16 tiling
// wasted 12.5% of all MMAs on out-of-image columns) + occupancy 4 ==
// CTA: 64 px (8h x 8w) x 128 outch. 256 thr, 8 warps (2M x 4N), warp tile
// 32px x 32oc -> acc only 16 regs -> ~58 live -> 4 CTAs/SM (8 warps/SMSP).
//   A: SMEM halo 10x10 px, padded-linear 144B rows, ldmatrix, loaded once.
//   B: 16KB/tap 2-stage SMEM ring via cp.async (zero reg pressure),
//      immediate-offset lds64 reads, 2 barriers/tap.
// Plateau context: R6/R10/R11/R12 all pinned at tensor=63% (~22.5cyc/QMMA
// effective) regardless of inner-loop form => reduce MMA count + add warps.
// (tcgen05/TMEM unavailable: harness ptxas targets base sm_103 — proven R1.)
// ============================================================================

constexpr int X_ELEMS = 64 * 56 * 56 * 128;   // 25,690,112
constexpr int WF_U4   = 9 * 32 * 2 * 32;      // 18,432 uint4 = 294,912 B
constexpr int X_BLOCKS = X_ELEMS / 8 / 256;   // 12,544

__device__ uint8_t g_xq[X_ELEMS];             // binarized x, NHWC e4m3
__device__ uint4   g_wf[WF_U4];               // weights, fragment-ordered

// ---------------------------------------------------------------------------
// merged preprocessing: e4m3 +1.0 = 0x38, -1.0 = 0xB8
// ---------------------------------------------------------------------------
__global__ void prep_kernel(const float* __restrict__ x,
                            const float* __restrict__ w) {
    if (blockIdx.x < X_BLOCKS) {
        int t = blockIdx.x * 256 + threadIdx.x;
        int base = t * 8;
        const float4* p = reinterpret_cast<const float4*>(x + base);
        float4 v0 = p[0], v1 = p[1];
        uint32_t lo = (v0.x >= 0.0f ? 0x38u : 0xB8u)        |
                      ((v0.y >= 0.0f ? 0x38u : 0xB8u) << 8)  |
                      ((v0.z >= 0.0f ? 0x38u : 0xB8u) << 16) |
                      ((v0.w >= 0.0f ? 0x38u : 0xB8u) << 24);
        uint32_t hi = (v1.x >= 0.0f ? 0x38u : 0xB8u)        |
                      ((v1.y >= 0.0f ? 0x38u : 0xB8u) << 8)  |
                      ((v1.z >= 0.0f ? 0x38u : 0xB8u) << 16) |
                      ((v1.w >= 0.0f ? 0x38u : 0xB8u) << 24);
        *reinterpret_cast<uint2*>(g_xq + base) = make_uint2(lo, hi);
    } else {
        // fragment order: u4 = ((tap*32 + g)*2 + kk)*32 + lane
        //   outch o = g*8 + (lane>>2)
        //   {x,y} = B-frag regs for k=2kk, {z,w} for k=2kk+1 (m16n8k32 colB)
        int u = (blockIdx.x - X_BLOCKS) * 256 + threadIdx.x;
        if (u >= WF_U4) return;
        int lane = u & 31;
        int kk   = (u >> 5) & 1;
        int g    = (u >> 6) & 31;
        int tap  = u >> 11;
        int o = g * 8 + (lane >> 2);
        uint32_t r[4];
        #pragma unroll
        for (int kp = 0; kp < 2; ++kp) {
            int cb = (2 * kk + kp) * 32 + (lane & 3) * 4;
            uint32_t r0 = 0, r1 = 0;
            #pragma unroll
            for (int b2 = 0; b2 < 4; ++b2) {
                float v0 = w[(tap * 128 + cb + b2) * 256 + o];       // HWIO
                float v1 = w[(tap * 128 + cb + 16 + b2) * 256 + o];
                r0 |= (v0 >= 0.0f ? 0x38u : 0xB8u) << (8 * b2);
                r1 |= (v1 >= 0.0f ? 0x38u : 0xB8u) << (8 * b2);
            }
            r[2 * kp] = r0; r[2 * kp + 1] = r1;
        }
        g_wf[u] = make_uint4(r[0], r[1], r[2], r[3]);
    }
}

// ---------------------------------------------------------------------------
// PTX helpers
// ---------------------------------------------------------------------------
static __device__ __forceinline__ void ldmatrix_x4(uint32_t* r, uint32_t addr) {
    asm volatile("ldmatrix.sync.aligned.m8n8.x4.shared.b16 {%0,%1,%2,%3}, [%4];"
                 : "=r"(r[0]), "=r"(r[1]), "=r"(r[2]), "=r"(r[3]) : "r"(addr));
}

// ld.shared.v2.u32 with compile-time immediate offset (no address ALU in SASS)
template <int IMM>
static __device__ __forceinline__ void lds64i(uint32_t& x, uint32_t& y,
                                              uint32_t base) {
    asm volatile("ld.shared.v2.u32 {%0,%1}, [%2+%3];"
                 : "=r"(x), "=r"(y) : "r"(base), "n"(IMM));
}

// fp8 MMA with f16 accumulators (2 regs, exact for integer sums < 2048)
static __device__ __forceinline__ void mma_fp8_h(uint32_t* c, const uint32_t* a,
                                                 uint32_t b0, uint32_t b1) {
    asm volatile(
        "mma.sync.aligned.m16n8k32.row.col.f16.e4m3.e4m3.f16 "
        "{%0,%1}, {%2,%3,%4,%5}, {%6,%7}, {%0,%1};"
        : "+r"(c[0]), "+r"(c[1])
        : "r"(a[0]), "r"(a[1]), "r"(a[2]), "r"(a[3]), "r"(b0), "r"(b1));
}

static __device__ __forceinline__ void cp16(uint32_t dst, const void* src, int srcsize) {
    asm volatile("cp.async.cg.shared.global [%0], [%1], 16, %2;"
                 :: "r"(dst), "l"(src), "r"(srcsize) : "memory");
}

// ---------------------------------------------------------------------------
// inner loop: kp-major, B rotated one step ahead, all-immediate LDS
//   B stage layout (per CTA): byte = g*1024 + kk*512 + lane*16 + kp*8
//   warp reads g = warp_n*4 + ni, ni = 0..3
// ---------------------------------------------------------------------------
template <int KK, int KP, int NI>
static __device__ __forceinline__ void ni_step(uint32_t (&acc)[2][4][2],
                                               const uint32_t (&a)[2][2][4],
                                               uint32_t bstage,
                                               uint32_t b0, uint32_t b1) {
    uint32_t n0 = 0, n1 = 0;
    if constexpr (NI < 3) {
        lds64i<(NI + 1) * 1024 + KK * 512 + KP * 8>(n0, n1, bstage);
    } else if constexpr (KP == 0) {
        lds64i<KK * 512 + 8>(n0, n1, bstage);         // first bv of kp=1
    }
    mma_fp8_h(acc[0][NI], a[KP][0], b0, b1);
    mma_fp8_h(acc[1][NI], a[KP][1], b0, b1);
    if constexpr (NI < 3)       ni_step<KK, KP, NI + 1>(acc, a, bstage, n0, n1);
    else if constexpr (KP == 0) ni_step<KK, 1, 0>(acc, a, bstage, n0, n1);
}

template <int KK>
static __device__ __forceinline__ void kk_step(uint32_t (&acc)[2][4][2],
                                               uint32_t atap0, uint32_t atap1,
                                               uint32_t bstage) {
    uint32_t a[2][2][4];                               // [kp][mi][4]
    ldmatrix_x4(a[0][0], atap0 + (2 * KK + 0) * 32);
    ldmatrix_x4(a[0][1], atap1 + (2 * KK + 0) * 32);
    ldmatrix_x4(a[1][0], atap0 + (2 * KK + 1) * 32);
    ldmatrix_x4(a[1][1], atap1 + (2 * KK + 1) * 32);
    uint32_t b0, b1;
    lds64i<KK * 512>(b0, b1, bstage);                  // bv for kp=0, ni=0
    ni_step<KK, 0, 0>(acc, a, bstage, b0, b1);
}

// ---------------------------------------------------------------------------
// main kernel: 256 threads, 8 warps (2M x 4N), warp tile 32px x 32oc
// SMEM: A halo 100 rows x 144B = 14,400 + B ring 2 x 16,384 = 47,168 total
// ---------------------------------------------------------------------------
constexpr int ROWB = 144;
constexpr int BOFF = 14400;                   // 16-aligned
constexpr int BSTG = 16384;                   // one B stage (128 outch x 128 ch)
constexpr int SMEM_TOTAL = BOFF + 2 * BSTG;   // 47,168

__global__ void __launch_bounds__(256, 4)
conv_fp8_kernel(float* __restrict__ out) {
    extern __shared__ char smem[];
    uint32_t sbase = (uint32_t)__cvta_generic_to_shared(smem);

    int tid  = threadIdx.x;
    int lane = tid & 31;
    int wid  = tid >> 5;
    int warp_m = wid & 1;        // 0..1 -> 32 pixels each
    int warp_n = wid >> 1;       // 0..3 -> 32 outch each

    // tile decode: blockIdx = ((img*49 + ht*7 + wt) << 1) | ntile
    int b = blockIdx.x;
    int ntile = b & 1;
    int mt = b >> 1;
    int img = mt / 49;
    int rr  = mt - img * 49;
    int ht  = rr / 7;
    int wt  = rr - ht * 7;
    int h0 = ht * 8;
    int w0 = wt * 8;
    int n0 = ntile * 128;

    // per-thread B staging assignment: 64B each (16KB / 256 threads)
    const char* wsrc0 = (const char*)g_wf + (uint32_t)(ntile * 16384 + tid * 64);
    uint32_t bdst = sbase + BOFF + (uint32_t)(tid * 64);

    // ---- stage A halo (10h x 10w pixels, zero-filled outside image) ----
    for (int idx = tid; idx < 800; idx += 256) {         // 100 rows x 8 chunks
        int row = idx >> 3, ch = idx & 7;
        int hr = row / 10;
        int wc = row - hr * 10;
        int hh = h0 + hr - 1;
        int ww = w0 + wc - 1;
        bool v = ((unsigned)hh < 56u) && ((unsigned)ww < 56u);
        const char* src = v ? (const char*)(g_xq + (((img * 56 + hh) * 56 + ww) << 7))
                            : (const char*)g_xq;
        cp16(sbase + row * ROWB + ch * 16, src + ch * 16, v ? 16 : 0);
    }
    // ---- stage B tap0 into stage 0 (same group as halo) ----
    #pragma unroll
    for (int i = 0; i < 4; ++i)
        cp16(bdst + i * 16, wsrc0 + i * 16, 16);
    asm volatile("cp.async.commit_group;" ::: "memory");          // G0: halo+B0
    // ---- stage B tap1 into stage 1 ----
    #pragma unroll
    for (int i = 0; i < 4; ++i)
        cp16(bdst + BSTG + i * 16, wsrc0 + 32768 + i * 16, 16);
    asm volatile("cp.async.commit_group;" ::: "memory");          // G1: B1

    // ---- per-lane ldmatrix base addresses (linear, conflict-free) ----
    int lane15 = lane & 15;
    int lanehi = lane >> 4;
    uint32_t abase[2];
    #pragma unroll
    for (int mi = 0; mi < 2; ++mi) {
        int p = warp_m * 32 + mi * 16 + lane15;          // pixel index 0..63
        int hrow = (p >> 3) * 10 + (p & 7);              // halo row at tap (0,0)
        abase[mi] = sbase + hrow * ROWB + lanehi * 16;
    }
    // B read base within a stage: + ni*1024 + kk*512 + kp*8 (immediates)
    uint32_t bthr = sbase + BOFF + (uint32_t)(warp_n * 4096 + lane * 16);

    uint32_t acc[2][4][2];                               // f16x2 accumulators
    #pragma unroll
    for (int mi = 0; mi < 2; ++mi)
        #pragma unroll
        for (int ni = 0; ni < 4; ++ni) {
            acc[mi][ni][0] = 0u; acc[mi][ni][1] = 0u;
        }

    // ---- mainloop: 9 taps, 2-stage B ring, 2 barriers/tap ----
    int tapoff = 0;   // kh*10 + kw
    int kw = 0;
    for (int tap = 0; tap < 9; ++tap) {
        if (tap < 8) { asm volatile("cp.async.wait_group 1;" ::: "memory"); }
        else         { asm volatile("cp.async.wait_group 0;" ::: "memory"); }
        __syncthreads();                                  // B(tap) visible to all

        uint32_t atap0 = abase[0] + (uint32_t)(tapoff * ROWB);
        uint32_t atap1 = abase[1] + (uint32_t)(tapoff * ROWB);
        uint32_t bstage = bthr + (uint32_t)((tap & 1) * BSTG);
        kk_step<0>(acc, atap0, atap1, bstage);
        kk_step<1>(acc, atap0, atap1, bstage);
        __syncthreads();                                  // stage tap&1 fully read

        if (tap + 2 <= 8) {                               // refill the stage just read
            const char* wsrc = wsrc0 + (uint32_t)((tap + 2) * 32768);
            uint32_t dst = bdst + (uint32_t)((tap & 1) * BSTG);
            #pragma unroll
            for (int i = 0; i < 4; ++i)
                cp16(dst + i * 16, wsrc + i * 16, 16);
            asm volatile("cp.async.commit_group;" ::: "memory");
        }

        if (kw == 2) { kw = 0; tapoff += 8; }            // +10 - 2
        else         { kw++;   tapoff += 1; }
    }

    // ---- epilogue: f16x2 -> f32 stores (exact; all 64 px in-image) ----
    int colbase = n0 + warp_n * 32 + (lane & 3) * 2;
    #pragma unroll
    for (int mi = 0; mi < 2; ++mi) {
        #pragma unroll
        for (int half = 0; half < 2; ++half) {
            int p = warp_m * 32 + mi * 16 + half * 8 + (lane >> 2);
            int hh = h0 + (p >> 3);
            int ww = w0 + (p & 7);
            float* op = out + (((img * 56 + hh) * 56 + ww) << 8);
            #pragma unroll
            for (int ni = 0; ni < 4; ++ni) {
                __half2 h = *reinterpret_cast<__half2*>(&acc[mi][ni][half]);
                float2 v = __half22float2(h);
                *reinterpret_cast<float2*>(op + colbase + ni * 8) = v;
            }
        }
    }
}

// ---------------------------------------------------------------------------
// launch
// ---------------------------------------------------------------------------
extern "C" void kernel_launch(void* const* d_in, const int* in_sizes, int n_in,
                              void* d_out, int out_size) {
    const float* x = (const float*)d_in[0];
    const float* w = (const float*)d_in[1];
    float* out = (float*)d_out;

    prep_kernel<<<X_BLOCKS + (WF_U4 + 255) / 256, 256>>>(x, w);

    cudaFuncSetAttribute(conv_fp8_kernel,
                         cudaFuncAttributeMaxDynamicSharedMemorySize, SMEM_TOTAL);
    // 64 images * 7 h-tiles * 7 w-tiles * 2 n-tiles = 6272 CTAs (zero waste)
    conv_fp8_kernel<<<6272, 256, SMEM_TOTAL>>>(out);
}

// round 14
// speedup vs baseline: 1.2697x; 1.2697x over previous
#include <cuda_runtime.h>
#include <cuda_fp16.h>
#include <cstdint>

// ============================================================================
// BinaryConv2D: x(64,56,56,128) NHWC conv w(3,3,128,256) HWIO, SAME, stride 1.
// binarize both -> implicit GEMM on mma.sync m16n8k32 e4m3, F16 accumulate
// (exact: products ±1, partial sums are integers <= 1152 < 2048).
// == R14: zero-waste 8x8 pixel tile (56 = 7x8) with R10's PROVEN warp-level
// structure untouched: warp tile 32px x 64oc, mi=2/ni=8, B via LDG ==
// CTA: 64 px (8h x 8w) x 256 outch. 256 thr, 8 warps (2M x 4N), 3 CTAs/SM.
// Work per CTA identical to R10 (64x256 == 128x128); grid 3136 vs 3584
// -> total MMA count -12.5% with the MMA:overhead ratio unchanged.
//   A: SMEM halo 10x10 px (14.4KB), padded-linear 144B rows, ldmatrix,
//      loaded once, NO mainloop barriers, tap loop ROLLED.
//   B: no smem; fragment-ordered weights, uint4 = 2 k-steps x 1 n-group,
//      __ldg right before use (short live ranges; R9 proved batching=>spill).
// Plateau context: R6/R10/R11/R12 pinned at tensor=63% (~15cyc/QMMA pipe
// rate => ~220us wall at 100%); this round cuts MMA count instead.
// (tcgen05/TMEM unavailable: harness ptxas targets base sm_103 — proven R1.)
// ============================================================================

constexpr int X_ELEMS = 64 * 56 * 56 * 128;   // 25,690,112
constexpr int WF_U4   = 9 * 32 * 2 * 32;      // 18,432 uint4 = 294,912 B
constexpr int X_BLOCKS = X_ELEMS / 8 / 256;   // 12,544

__device__ uint8_t g_xq[X_ELEMS];             // binarized x, NHWC e4m3
__device__ uint4   g_wf[WF_U4];               // weights, fragment-ordered

// ---------------------------------------------------------------------------
// merged preprocessing: e4m3 +1.0 = 0x38, -1.0 = 0xB8
// ---------------------------------------------------------------------------
__global__ void prep_kernel(const float* __restrict__ x,
                            const float* __restrict__ w) {
    if (blockIdx.x < X_BLOCKS) {
        int t = blockIdx.x * 256 + threadIdx.x;
        int base = t * 8;
        const float4* p = reinterpret_cast<const float4*>(x + base);
        float4 v0 = p[0], v1 = p[1];
        uint32_t lo = (v0.x >= 0.0f ? 0x38u : 0xB8u)        |
                      ((v0.y >= 0.0f ? 0x38u : 0xB8u) << 8)  |
                      ((v0.z >= 0.0f ? 0x38u : 0xB8u) << 16) |
                      ((v0.w >= 0.0f ? 0x38u : 0xB8u) << 24);
        uint32_t hi = (v1.x >= 0.0f ? 0x38u : 0xB8u)        |
                      ((v1.y >= 0.0f ? 0x38u : 0xB8u) << 8)  |
                      ((v1.z >= 0.0f ? 0x38u : 0xB8u) << 16) |
                      ((v1.w >= 0.0f ? 0x38u : 0xB8u) << 24);
        *reinterpret_cast<uint2*>(g_xq + base) = make_uint2(lo, hi);
    } else {
        // fragment order: u4 = ((tap*32 + g)*2 + kk)*32 + lane
        //   outch o = g*8 + (lane>>2),  g = 0..31 covers all 256 outch
        //   {x,y} = B-frag regs for k=2kk, {z,w} for k=2kk+1 (m16n8k32 colB)
        int u = (blockIdx.x - X_BLOCKS) * 256 + threadIdx.x;
        if (u >= WF_U4) return;
        int lane = u & 31;
        int kk   = (u >> 5) & 1;
        int g    = (u >> 6) & 31;
        int tap  = u >> 11;
        int o = g * 8 + (lane >> 2);
        uint32_t r[4];
        #pragma unroll
        for (int kp = 0; kp < 2; ++kp) {
            int cb = (2 * kk + kp) * 32 + (lane & 3) * 4;
            uint32_t r0 = 0, r1 = 0;
            #pragma unroll
            for (int b2 = 0; b2 < 4; ++b2) {
                float v0 = w[(tap * 128 + cb + b2) * 256 + o];       // HWIO
                float v1 = w[(tap * 128 + cb + 16 + b2) * 256 + o];
                r0 |= (v0 >= 0.0f ? 0x38u : 0xB8u) << (8 * b2);
                r1 |= (v1 >= 0.0f ? 0x38u : 0xB8u) << (8 * b2);
            }
            r[2 * kp] = r0; r[2 * kp + 1] = r1;
        }
        g_wf[u] = make_uint4(r[0], r[1], r[2], r[3]);
    }
}

// ---------------------------------------------------------------------------
// PTX helpers
// ---------------------------------------------------------------------------
static __device__ __forceinline__ void ldmatrix_x4(uint32_t& r0, uint32_t& r1,
                                                   uint32_t& r2, uint32_t& r3,
                                                   uint32_t addr) {
    asm volatile("ldmatrix.sync.aligned.m8n8.x4.shared.b16 {%0,%1,%2,%3}, [%4];"
                 : "=r"(r0), "=r"(r1), "=r"(r2), "=r"(r3) : "r"(addr));
}

// fp8 MMA with f16 accumulators (2 regs, exact for integer sums < 2048)
static __device__ __forceinline__ void mma_fp8_h(uint32_t* c, const uint32_t* a,
                                                 uint32_t b0, uint32_t b1) {
    asm volatile(
        "mma.sync.aligned.m16n8k32.row.col.f16.e4m3.e4m3.f16 "
        "{%0,%1}, {%2,%3,%4,%5}, {%6,%7}, {%0,%1};"
        : "+r"(c[0]), "+r"(c[1])
        : "r"(a[0]), "r"(a[1]), "r"(a[2]), "r"(a[3]), "r"(b0), "r"(b1));
}

static __device__ __forceinline__ void cp16(uint32_t dst, const void* src, int srcsize) {
    asm volatile("cp.async.cg.shared.global [%0], [%1], 16, %2;"
                 :: "r"(dst), "l"(src), "r"(srcsize) : "memory");
}

// ---------------------------------------------------------------------------
// main kernel: 256 threads, 8 warps (2M x 4N), warp tile 32px x 64oc
// SMEM: A halo only, 100 rows x 144B stride = 14,400 B
// ---------------------------------------------------------------------------
constexpr int ROWB = 144;
constexpr int SMEM_TOTAL = 100 * ROWB;        // 14,400

__global__ void __launch_bounds__(256, 3)
conv_fp8_kernel(float* __restrict__ out) {
    extern __shared__ char smem[];
    uint32_t sbase = (uint32_t)__cvta_generic_to_shared(smem);

    int tid  = threadIdx.x;
    int lane = tid & 31;
    int wid  = tid >> 5;
    int warp_m = wid & 1;        // 0..1 -> 32 pixels each
    int warp_n = wid >> 1;       // 0..3 -> 64 outch each

    // tile decode: blockIdx = img*49 + ht*7 + wt   (zero-waste 8x8 tiles)
    int b = blockIdx.x;
    int img = b / 49;
    int rr  = b - img * 49;
    int ht  = rr / 7;
    int wt  = rr - ht * 7;
    int h0 = ht * 8;
    int w0 = wt * 8;

    // ---- stage A halo (10h x 10w pixels, zero-filled outside image) ----
    for (int idx = tid; idx < 800; idx += 256) {         // 100 rows x 8 chunks
        int row = idx >> 3, ch = idx & 7;
        int hr = row / 10;
        int wc = row - hr * 10;
        int hh = h0 + hr - 1;
        int ww = w0 + wc - 1;
        bool v = ((unsigned)hh < 56u) && ((unsigned)ww < 56u);
        const char* src = v ? (const char*)(g_xq + (((img * 56 + hh) * 56 + ww) << 7))
                            : (const char*)g_xq;
        cp16(sbase + row * ROWB + ch * 16, src + ch * 16, v ? 16 : 0);
    }
    asm volatile("cp.async.commit_group;" ::: "memory");
    asm volatile("cp.async.wait_group 0;" ::: "memory");
    __syncthreads();

    // ---- per-lane ldmatrix base addresses (linear, conflict-free) ----
    int lane15 = lane & 15;
    int lanehi = lane >> 4;
    uint32_t abase[2];
    #pragma unroll
    for (int mi = 0; mi < 2; ++mi) {
        int p = warp_m * 32 + mi * 16 + lane15;          // pixel index 0..63
        int hrow = (p >> 3) * 10 + (p & 7);              // halo row at tap (0,0)
        abase[mi] = sbase + hrow * ROWB + lanehi * 16;
    }
    // B fragment base for this thread: g = warp_n*8 + ni
    const uint4* wf0 = g_wf + (uint32_t)(((warp_n * 8) * 2) * 32 + lane);

    uint32_t acc[2][8][2];                               // f16x2 accumulators
    #pragma unroll
    for (int mi = 0; mi < 2; ++mi)
        #pragma unroll
        for (int ni = 0; ni < 8; ++ni) {
            acc[mi][ni][0] = 0u; acc[mi][ni][1] = 0u;
        }

    // ---- mainloop: 9 taps (ROLLED) x 2 kk, no barriers, no smem writes ----
    int tapoff = 0;   // kh*10 + kw
    int kw = 0;
    for (int tap = 0; tap < 9; ++tap) {
        const uint4* wft = wf0 + (uint32_t)(tap * 64 * 32);
        uint32_t atap0 = abase[0] + (uint32_t)(tapoff * ROWB);
        uint32_t atap1 = abase[1] + (uint32_t)(tapoff * ROWB);
        #pragma unroll
        for (int kk = 0; kk < 2; ++kk) {
            uint32_t a[2][2][4];                          // [kpar][mi][4]
            #pragma unroll
            for (int kp = 0; kp < 2; ++kp) {
                uint32_t koff = (uint32_t)((2 * kk + kp) * 32);  // LDSM immediate
                ldmatrix_x4(a[kp][0][0], a[kp][0][1], a[kp][0][2], a[kp][0][3],
                            atap0 + koff);
                ldmatrix_x4(a[kp][1][0], a[kp][1][1], a[kp][1][2], a[kp][1][3],
                            atap1 + koff);
            }
            const uint4* wfk = wft + (uint32_t)(kk * 32);
            #pragma unroll
            for (int ni = 0; ni < 8; ++ni) {
                uint4 bv = __ldg(wfk + ni * 64);          // g stride = 2*32 u4
                mma_fp8_h(acc[0][ni], a[0][0], bv.x, bv.y);
                mma_fp8_h(acc[1][ni], a[0][1], bv.x, bv.y);
                mma_fp8_h(acc[0][ni], a[1][0], bv.z, bv.w);
                mma_fp8_h(acc[1][ni], a[1][1], bv.z, bv.w);
            }
        }
        if (kw == 2) { kw = 0; tapoff += 8; }            // +10 - 2
        else         { kw++;   tapoff += 1; }
    }

    // ---- epilogue: f16x2 -> f32 stores (exact; all 64 px in-image) ----
    int colbase = warp_n * 64 + (lane & 3) * 2;
    #pragma unroll
    for (int mi = 0; mi < 2; ++mi) {
        #pragma unroll
        for (int half = 0; half < 2; ++half) {
            int p = warp_m * 32 + mi * 16 + half * 8 + (lane >> 2);
            int hh = h0 + (p >> 3);
            int ww = w0 + (p & 7);
            float* op = out + (((img * 56 + hh) * 56 + ww) << 8);
            #pragma unroll
            for (int ni = 0; ni < 8; ++ni) {
                __half2 h = *reinterpret_cast<__half2*>(&acc[mi][ni][half]);
                float2 v = __half22float2(h);
                *reinterpret_cast<float2*>(op + colbase + ni * 8) = v;
            }
        }
    }
}

// ---------------------------------------------------------------------------
// launch
// ---------------------------------------------------------------------------
extern "C" void kernel_launch(void* const* d_in, const int* in_sizes, int n_in,
                              void* d_out, int out_size) {
    const float* x = (const float*)d_in[0];
    const float* w = (const float*)d_in[1];
    float* out = (float*)d_out;

    prep_kernel<<<X_BLOCKS + (WF_U4 + 255) / 256, 256>>>(x, w);

    cudaFuncSetAttribute(conv_fp8_kernel,
                         cudaFuncAttributeMaxDynamicSharedMemorySize, SMEM_TOTAL);
    // 64 images * 7 h-tiles * 7 w-tiles = 3136 CTAs (zero wasted MMAs)
    conv_fp8_kernel<<<3136, 256, SMEM_TOTAL>>>(out);
}

// round 15
// speedup vs baseline: 1.2810x; 1.0089x over previous
#include <cuda_runtime.h>
#include <cuda_fp16.h>
#include <cstdint>

// ============================================================================
// BinaryConv2D: x(64,56,56,128) NHWC conv w(3,3,128,256) HWIO, SAME, stride 1.
// binarize both -> implicit GEMM on mma.sync m16n8k32 e4m3, F16 accumulate
// (exact: products ±1, partial sums are integers <= 1152 < 2048).
// == R15: R14 (best, 326.4us) + 3x3 tap unroll: kh loop x3, kw fully
// unrolled -> kw offsets become LDSM immediates, 2/3 of branches gone,
// 6-kk-step scheduling window. Live state unchanged (no B batching!). ==
// CTA: 64 px (8h x 8w, zero waste since 56=7x8) x 256 outch. 256 thr,
// 8 warps (2M x 4N), warp tile 32px x 64oc, 3 CTAs/SM.
//   A: SMEM halo 10x10 px (14.4KB), padded-linear 144B rows, ldmatrix,
//      loaded once, NO mainloop barriers.
//   B: no smem; fragment-ordered weights, uint4 = 2 k-steps x 1 n-group,
//      __ldg right before use (short live ranges; R9: batching => spills).
// Rate-pin context: tensor% locked ~62% across 8 structural variants
// (~23cyc/QMMA eff vs ~14.5 pipe floor); this targets issue overhead.
// (tcgen05/TMEM unavailable: harness ptxas targets base sm_103 — proven R1.)
// ============================================================================

constexpr int X_ELEMS = 64 * 56 * 56 * 128;   // 25,690,112
constexpr int WF_U4   = 9 * 32 * 2 * 32;      // 18,432 uint4 = 294,912 B
constexpr int X_BLOCKS = X_ELEMS / 8 / 256;   // 12,544

__device__ uint8_t g_xq[X_ELEMS];             // binarized x, NHWC e4m3
__device__ uint4   g_wf[WF_U4];               // weights, fragment-ordered

// ---------------------------------------------------------------------------
// merged preprocessing: e4m3 +1.0 = 0x38, -1.0 = 0xB8
// ---------------------------------------------------------------------------
__global__ void prep_kernel(const float* __restrict__ x,
                            const float* __restrict__ w) {
    if (blockIdx.x < X_BLOCKS) {
        int t = blockIdx.x * 256 + threadIdx.x;
        int base = t * 8;
        const float4* p = reinterpret_cast<const float4*>(x + base);
        float4 v0 = p[0], v1 = p[1];
        uint32_t lo = (v0.x >= 0.0f ? 0x38u : 0xB8u)        |
                      ((v0.y >= 0.0f ? 0x38u : 0xB8u) << 8)  |
                      ((v0.z >= 0.0f ? 0x38u : 0xB8u) << 16) |
                      ((v0.w >= 0.0f ? 0x38u : 0xB8u) << 24);
        uint32_t hi = (v1.x >= 0.0f ? 0x38u : 0xB8u)        |
                      ((v1.y >= 0.0f ? 0x38u : 0xB8u) << 8)  |
                      ((v1.z >= 0.0f ? 0x38u : 0xB8u) << 16) |
                      ((v1.w >= 0.0f ? 0x38u : 0xB8u) << 24);
        *reinterpret_cast<uint2*>(g_xq + base) = make_uint2(lo, hi);
    } else {
        // fragment order: u4 = ((tap*32 + g)*2 + kk)*32 + lane
        //   outch o = g*8 + (lane>>2),  g = 0..31 covers all 256 outch
        //   {x,y} = B-frag regs for k=2kk, {z,w} for k=2kk+1 (m16n8k32 colB)
        int u = (blockIdx.x - X_BLOCKS) * 256 + threadIdx.x;
        if (u >= WF_U4) return;
        int lane = u & 31;
        int kk   = (u >> 5) & 1;
        int g    = (u >> 6) & 31;
        int tap  = u >> 11;
        int o = g * 8 + (lane >> 2);
        uint32_t r[4];
        #pragma unroll
        for (int kp = 0; kp < 2; ++kp) {
            int cb = (2 * kk + kp) * 32 + (lane & 3) * 4;
            uint32_t r0 = 0, r1 = 0;
            #pragma unroll
            for (int b2 = 0; b2 < 4; ++b2) {
                float v0 = w[(tap * 128 + cb + b2) * 256 + o];       // HWIO
                float v1 = w[(tap * 128 + cb + 16 + b2) * 256 + o];
                r0 |= (v0 >= 0.0f ? 0x38u : 0xB8u) << (8 * b2);
                r1 |= (v1 >= 0.0f ? 0x38u : 0xB8u) << (8 * b2);
            }
            r[2 * kp] = r0; r[2 * kp + 1] = r1;
        }
        g_wf[u] = make_uint4(r[0], r[1], r[2], r[3]);
    }
}

// ---------------------------------------------------------------------------
// PTX helpers
// ---------------------------------------------------------------------------
static __device__ __forceinline__ void ldmatrix_x4(uint32_t& r0, uint32_t& r1,
                                                   uint32_t& r2, uint32_t& r3,
                                                   uint32_t addr) {
    asm volatile("ldmatrix.sync.aligned.m8n8.x4.shared.b16 {%0,%1,%2,%3}, [%4];"
                 : "=r"(r0), "=r"(r1), "=r"(r2), "=r"(r3) : "r"(addr));
}

// fp8 MMA with f16 accumulators (2 regs, exact for integer sums < 2048)
static __device__ __forceinline__ void mma_fp8_h(uint32_t* c, const uint32_t* a,
                                                 uint32_t b0, uint32_t b1) {
    asm volatile(
        "mma.sync.aligned.m16n8k32.row.col.f16.e4m3.e4m3.f16 "
        "{%0,%1}, {%2,%3,%4,%5}, {%6,%7}, {%0,%1};"
        : "+r"(c[0]), "+r"(c[1])
        : "r"(a[0]), "r"(a[1]), "r"(a[2]), "r"(a[3]), "r"(b0), "r"(b1));
}

static __device__ __forceinline__ void cp16(uint32_t dst, const void* src, int srcsize) {
    asm volatile("cp.async.cg.shared.global [%0], [%1], 16, %2;"
                 :: "r"(dst), "l"(src), "r"(srcsize) : "memory");
}

// ---------------------------------------------------------------------------
// main kernel: 256 threads, 8 warps (2M x 4N), warp tile 32px x 64oc
// SMEM: A halo only, 100 rows x 144B stride = 14,400 B
// ---------------------------------------------------------------------------
constexpr int ROWB = 144;
constexpr int SMEM_TOTAL = 100 * ROWB;        // 14,400

__global__ void __launch_bounds__(256, 3)
conv_fp8_kernel(float* __restrict__ out) {
    extern __shared__ char smem[];
    uint32_t sbase = (uint32_t)__cvta_generic_to_shared(smem);

    int tid  = threadIdx.x;
    int lane = tid & 31;
    int wid  = tid >> 5;
    int warp_m = wid & 1;        // 0..1 -> 32 pixels each
    int warp_n = wid >> 1;       // 0..3 -> 64 outch each

    // tile decode: blockIdx = img*49 + ht*7 + wt   (zero-waste 8x8 tiles)
    int b = blockIdx.x;
    int img = b / 49;
    int rr  = b - img * 49;
    int ht  = rr / 7;
    int wt  = rr - ht * 7;
    int h0 = ht * 8;
    int w0 = wt * 8;

    // ---- stage A halo (10h x 10w pixels, zero-filled outside image) ----
    for (int idx = tid; idx < 800; idx += 256) {         // 100 rows x 8 chunks
        int row = idx >> 3, ch = idx & 7;
        int hr = row / 10;
        int wc = row - hr * 10;
        int hh = h0 + hr - 1;
        int ww = w0 + wc - 1;
        bool v = ((unsigned)hh < 56u) && ((unsigned)ww < 56u);
        const char* src = v ? (const char*)(g_xq + (((img * 56 + hh) * 56 + ww) << 7))
                            : (const char*)g_xq;
        cp16(sbase + row * ROWB + ch * 16, src + ch * 16, v ? 16 : 0);
    }
    asm volatile("cp.async.commit_group;" ::: "memory");
    asm volatile("cp.async.wait_group 0;" ::: "memory");
    __syncthreads();

    // ---- per-lane ldmatrix base addresses (linear, conflict-free) ----
    int lane15 = lane & 15;
    int lanehi = lane >> 4;
    uint32_t abase[2];
    #pragma unroll
    for (int mi = 0; mi < 2; ++mi) {
        int p = warp_m * 32 + mi * 16 + lane15;          // pixel index 0..63
        int hrow = (p >> 3) * 10 + (p & 7);              // halo row at tap (0,0)
        abase[mi] = sbase + hrow * ROWB + lanehi * 16;
    }
    // B fragment base for this thread: g = warp_n*8 + ni
    const uint4* wf0 = g_wf + (uint32_t)(((warp_n * 8) * 2) * 32 + lane);

    uint32_t acc[2][8][2];                               // f16x2 accumulators
    #pragma unroll
    for (int mi = 0; mi < 2; ++mi)
        #pragma unroll
        for (int ni = 0; ni < 8; ++ni) {
            acc[mi][ni][0] = 0u; acc[mi][ni][1] = 0u;
        }

    // ---- mainloop: kh x3 (rolled), kw x3 + kk x2 fully unrolled ----
    // kw offsets are LDSM immediates off the per-kh base; B tap pointers are
    // constant offsets off the per-kh pointer. No tapoff/kw update chain.
    for (int kh = 0; kh < 3; ++kh) {
        uint32_t akh0 = abase[0] + (uint32_t)(kh * 10 * ROWB);
        uint32_t akh1 = abase[1] + (uint32_t)(kh * 10 * ROWB);
        const uint4* wkh = wf0 + (uint32_t)(kh * 3 * 2048);  // 3 taps * 64*32
        #pragma unroll
        for (int kw = 0; kw < 3; ++kw) {
            const uint4* wft = wkh + (uint32_t)(kw * 2048);
            #pragma unroll
            for (int kk = 0; kk < 2; ++kk) {
                uint32_t a[2][2][4];                      // [kpar][mi][4]
                #pragma unroll
                for (int kp = 0; kp < 2; ++kp) {
                    uint32_t koff = (uint32_t)(kw * ROWB + (2 * kk + kp) * 32);
                    ldmatrix_x4(a[kp][0][0], a[kp][0][1], a[kp][0][2], a[kp][0][3],
                                akh0 + koff);
                    ldmatrix_x4(a[kp][1][0], a[kp][1][1], a[kp][1][2], a[kp][1][3],
                                akh1 + koff);
                }
                const uint4* wfk = wft + (uint32_t)(kk * 32);
                #pragma unroll
                for (int ni = 0; ni < 8; ++ni) {
                    uint4 bv = __ldg(wfk + ni * 64);      // g stride = 2*32 u4
                    mma_fp8_h(acc[0][ni], a[0][0], bv.x, bv.y);
                    mma_fp8_h(acc[1][ni], a[0][1], bv.x, bv.y);
                    mma_fp8_h(acc[0][ni], a[1][0], bv.z, bv.w);
                    mma_fp8_h(acc[1][ni], a[1][1], bv.z, bv.w);
                }
            }
        }
    }

    // ---- epilogue: f16x2 -> f32 stores (exact; all 64 px in-image) ----
    int colbase = warp_n * 64 + (lane & 3) * 2;
    #pragma unroll
    for (int mi = 0; mi < 2; ++mi) {
        #pragma unroll
        for (int half = 0; half < 2; ++half) {
            int p = warp_m * 32 + mi * 16 + half * 8 + (lane >> 2);
            int hh = h0 + (p >> 3);
            int ww = w0 + (p & 7);
            float* op = out + (((img * 56 + hh) * 56 + ww) << 8);
            #pragma unroll
            for (int ni = 0; ni < 8; ++ni) {
                __half2 h = *reinterpret_cast<__half2*>(&acc[mi][ni][half]);
                float2 v = __half22float2(h);
                *reinterpret_cast<float2*>(op + colbase + ni * 8) = v;
            }
        }
    }
}

// ---------------------------------------------------------------------------
// launch
// ---------------------------------------------------------------------------
extern "C" void kernel_launch(void* const* d_in, const int* in_sizes, int n_in,
                              void* d_out, int out_size) {
    const float* x = (const float*)d_in[0];
    const float* w = (const float*)d_in[1];
    float* out = (float*)d_out;

    prep_kernel<<<X_BLOCKS + (WF_U4 + 255) / 256, 256>>>(x, w);

    cudaFuncSetAttribute(conv_fp8_kernel,
                         cudaFuncAttributeMaxDynamicSharedMemorySize, SMEM_TOTAL);
    // 64 images * 7 h-tiles * 7 w-tiles = 3136 CTAs (zero wasted MMAs)
    conv_fp8_kernel<<<3136, 256, SMEM_TOTAL>>>(out);
}